// round 16
// baseline (speedup 1.0000x reference)
#include <cuda_runtime.h>

// Problem shape
#define B    4
#define T    8192
#define D    512
#define CH   32                // time steps per chunk (per block)
#define S    2                 // subtile steps (pipeline stage)
#define NS   (CH / S)          // 16 subtiles
#define NC   (T / CH)          // 256 chunks per sequence
#define TPB  128               // threads per block; each owns 4 channels

// Flag states
#define FLG_NONE 0
#define FLG_PREF 2

// Scratch (device globals; zero-initialized at module load).
__device__ float g_prefh[B * NC * D];        // per-chunk inclusive-prefix h
__device__ int   g_flag [B * NC * TPB];      // per-(b, chunk, thread)

__device__ __forceinline__ float tanha(float x) {
    float y;
    asm("tanh.approx.f32 %0, %1;" : "=f"(y) : "f"(x));
    return y;
}
__device__ __forceinline__ float sigm(float x) {
    return fmaf(tanha(0.5f * x), 0.5f, 0.5f);
}
__device__ __forceinline__ void st_release(int* p, int v) {
    asm volatile("st.release.gpu.global.b32 [%0], %1;" :: "l"(p), "r"(v) : "memory");
}
__device__ __forceinline__ int ld_acquire(const int* p) {
    int v;
    asm volatile("ld.acquire.gpu.global.b32 %0, [%1];" : "=r"(v) : "l"(p) : "memory");
    return v;
}

__global__ void __launch_bounds__(TPB, 7)
scan_sweep(const float* __restrict__ x, float* __restrict__ out) {
    const int c   = blockIdx.x;          // chunk (predecessors have lower bid)
    const int b   = blockIdx.y;          // batch
    const int tid = threadIdx.x;
    const int ch  = tid * 4;             // channel base (owns 4)

    const float* base  = x   + ((size_t)b * T + (size_t)c * CH) * (3 * D) + ch;
    float*       obase = out + ((size_t)b * T + (size_t)c * CH) * D + ch;

    // Double-buffered register tiles (float4 = LDG.128 per stream per step).
    float4 V[2][S], G[2][S], O[2][S];

    // ---- Prologue: issue subtile 0 loads (in flight during the wait) ------
#pragma unroll
    for (int t = 0; t < S; ++t) {
        const size_t row = (size_t)t * (3 * D);
        V[0][t] = __ldcs((const float4*)(base + row));
        G[0][t] = __ldcs((const float4*)(base + row + D));
        O[0][t] = __ldcs((const float4*)(base + row + 2 * D));
    }

    // ---- Prefix first: wait for predecessor's published inclusive prefix --
    float h0 = 0.f, h1 = 0.f, h2 = 0.f, h3 = 0.f;
    if (c > 0) {
        const int fidx = (b * NC + (c - 1)) * TPB + tid;
        while (ld_acquire(&g_flag[fidx]) != FLG_PREF) { }
        const float4 pv = __ldcg((const float4*)&g_prefh[((size_t)b * NC + (c - 1)) * D + ch]);
        h0 = pv.x; h1 = pv.y; h2 = pv.z; h3 = pv.w;
    }

    // ---- Single pipelined sweep: load subtile s+1, compute+emit subtile s -
#pragma unroll
    for (int s = 0; s < NS; ++s) {
        const int cur = s & 1;
        const int nxt = cur ^ 1;

        if (s + 1 < NS) {
#pragma unroll
            for (int t = 0; t < S; ++t) {
                const size_t row = (size_t)((s + 1) * S + t) * (3 * D);
                V[nxt][t] = __ldcs((const float4*)(base + row));
                G[nxt][t] = __ldcs((const float4*)(base + row + D));
                O[nxt][t] = __ldcs((const float4*)(base + row + 2 * D));
            }
        }

#pragma unroll
        for (int t = 0; t < S; ++t) {
            const float4 vi = V[cur][t];
            const float4 gi = G[cur][t];
            const float4 go = O[cur][t];

            float i0 = sigm(gi.x), i1 = sigm(gi.y), i2 = sigm(gi.z), i3 = sigm(gi.w);
            float f0 = 1.f - i0,   f1 = 1.f - i1,   f2 = 1.f - i2,   f3 = 1.f - i3;
            float w0 = i0 * tanha(vi.x), w1 = i1 * tanha(vi.y);
            float w2 = i2 * tanha(vi.z), w3 = i3 * tanha(vi.w);

            h0 = fmaf(f0, h0, w0);
            h1 = fmaf(f1, h1, w1);
            h2 = fmaf(f2, h2, w2);
            h3 = fmaf(f3, h3, w3);

            float4 o4;
            o4.x = tanha(h0) * sigm(go.x);
            o4.y = tanha(h1) * sigm(go.y);
            o4.z = tanha(h2) * sigm(go.z);
            o4.w = tanha(h3) * sigm(go.w);
            __stcs((float4*)(obase + (size_t)(s * S + t) * D), o4);
        }
    }

    // ---- Publish inclusive prefix for successors ---------------------------
    __stcg((float4*)&g_prefh[((size_t)b * NC + c) * D + ch],
           make_float4(h0, h1, h2, h3));
    st_release(&g_flag[(b * NC + c) * TPB + tid], FLG_PREF);
}

extern "C" void kernel_launch(void* const* d_in, const int* in_sizes, int n_in,
                              void* d_out, int out_size) {
    const float* x = (const float*)d_in[0];
    float* out = (float*)d_out;

    dim3 grid(NC, B);   // 256 x 4 = 1024 blocks
    scan_sweep<<<grid, TPB>>>(x, out);
}

// round 17
// speedup vs baseline: 1.0293x; 1.0293x over previous
#include <cuda_runtime.h>

// Problem shape
#define B    4
#define T    8192
#define D    512
#define CH   32                // time steps per chunk (per block)
#define S    4                 // subtile steps (pipeline stage)
#define NS   (CH / S)          // 8 subtiles
#define NC   (T / CH)          // 256 chunks per sequence
#define TPB  128               // threads per block
#define NDG  2                 // D-groups (channel halves) per chunk
#define DG   (D / NDG)         // 256 channels per block

// Flag states
#define FLG_NONE 0
#define FLG_PREF 2

// Scratch (device globals; zero-initialized at module load).
__device__ float g_prefh[B * NC * D];             // per-chunk inclusive-prefix h
__device__ int   g_flag [B * NDG * NC * TPB];     // per-(b, dgroup, chunk, thread)

__device__ __forceinline__ float tanha(float x) {
    float y;
    asm("tanh.approx.f32 %0, %1;" : "=f"(y) : "f"(x));
    return y;
}
__device__ __forceinline__ float sigm(float x) {
    return fmaf(tanha(0.5f * x), 0.5f, 0.5f);
}
__device__ __forceinline__ void st_release(int* p, int v) {
    asm volatile("st.release.gpu.global.b32 [%0], %1;" :: "l"(p), "r"(v) : "memory");
}
__device__ __forceinline__ int ld_acquire(const int* p) {
    int v;
    asm volatile("ld.acquire.gpu.global.b32 %0, [%1];" : "=r"(v) : "l"(p) : "memory");
    return v;
}

__global__ void __launch_bounds__(TPB, 8)
scan_sweep(const float* __restrict__ x, float* __restrict__ out) {
    const int c   = blockIdx.x;          // chunk (predecessors have lower bid)
    const int dg  = blockIdx.y;          // channel half
    const int b   = blockIdx.z;          // batch
    const int tid = threadIdx.x;
    const int ch  = dg * DG + tid * 2;   // absolute channel base (owns 2)

    const float* base  = x   + ((size_t)b * T + (size_t)c * CH) * (3 * D) + ch;
    float*       obase = out + ((size_t)b * T + (size_t)c * CH) * D + ch;

    // V/G: double-buffered (distance-1 prefetch). O: single-buffered.
    float2 V[2][S], G[2][S];

    // ---- Prologue: issue subtile 0 V/G loads (in flight during the wait) --
#pragma unroll
    for (int t = 0; t < S; ++t) {
        const size_t row = (size_t)t * (3 * D);
        V[0][t] = __ldcs((const float2*)(base + row));
        G[0][t] = __ldcs((const float2*)(base + row + D));
    }

    // ---- Prefix first: wait for predecessor's published inclusive prefix --
    float h0 = 0.f, h1 = 0.f;
    if (c > 0) {
        const int fidx = ((b * NDG + dg) * NC + (c - 1)) * TPB + tid;
        while (ld_acquire(&g_flag[fidx]) != FLG_PREF) { }
        const float2 pv = __ldcg((const float2*)&g_prefh[((size_t)b * NC + (c - 1)) * D + ch]);
        h0 = pv.x; h1 = pv.y;
    }

    // ---- Single pipelined sweep ---------------------------------------------
#pragma unroll
    for (int s = 0; s < NS; ++s) {
        const int cur = s & 1;
        const int nxt = cur ^ 1;

        // O for the CURRENT subtile: issued before this subtile's compute.
        float2 O[S];
#pragma unroll
        for (int t = 0; t < S; ++t)
            O[t] = __ldcs((const float2*)(base + (size_t)(s * S + t) * (3 * D) + 2 * D));

        // V/G for the NEXT subtile: distance-1 prefetch.
        if (s + 1 < NS) {
#pragma unroll
            for (int t = 0; t < S; ++t) {
                const size_t row = (size_t)((s + 1) * S + t) * (3 * D);
                V[nxt][t] = __ldcs((const float2*)(base + row));
                G[nxt][t] = __ldcs((const float2*)(base + row + D));
            }
        }

#pragma unroll
        for (int t = 0; t < S; ++t) {
            const float2 vi = V[cur][t];
            const float2 gi = G[cur][t];
            const float2 go = O[t];

            float i0 = sigm(gi.x), i1 = sigm(gi.y);
            float f0 = 1.f - i0,   f1 = 1.f - i1;
            float w0 = i0 * tanha(vi.x), w1 = i1 * tanha(vi.y);

            h0 = fmaf(f0, h0, w0);
            h1 = fmaf(f1, h1, w1);

            float2 o2;
            o2.x = tanha(h0) * sigm(go.x);
            o2.y = tanha(h1) * sigm(go.y);
            __stcs((float2*)(obase + (size_t)(s * S + t) * D), o2);
        }
    }

    // ---- Publish inclusive prefix for successors ---------------------------
    __stcg((float2*)&g_prefh[((size_t)b * NC + c) * D + ch], make_float2(h0, h1));
    st_release(&g_flag[((b * NDG + dg) * NC + c) * TPB + tid], FLG_PREF);
}

extern "C" void kernel_launch(void* const* d_in, const int* in_sizes, int n_in,
                              void* d_out, int out_size) {
    const float* x = (const float*)d_in[0];
    float* out = (float*)d_out;

    dim3 grid(NC, NDG, B);   // 256 x 2 x 4 = 2048 blocks
    scan_sweep<<<grid, TPB>>>(x, out);
}